// round 1
// baseline (speedup 1.0000x reference)
#include <cuda_runtime.h>
#include <cuda_bf16.h>
#include <math.h>

// Problem constants
constexpr int Bb  = 4;
constexpr int LP  = 768;
constexpr int LE  = 256;
constexpr int Lt  = 1024;   // LP + LE
constexpr int DP  = 2048;
constexpr int DE  = 1024;
constexpr int Hh  = 8;
constexpr int HD  = 256;
constexpr int HH  = 2048;   // H * HD

// Scratch (allocation-free: static device globals)
__device__ float g_Q[(size_t)Bb * Lt * HH];        // 8.4M floats
__device__ float g_K[(size_t)Bb * Lt * HD];        // 1M
__device__ float g_V[(size_t)Bb * Lt * HD];        // 1M
__device__ float g_S[(size_t)Bb * Hh * Lt * Lt];   // 33.5M (scores / probs)
__device__ float g_AO[(size_t)Bb * Lt * HH];       // 8.4M (attention output)

// ---------------------------------------------------------------------------
// Tiled SGEMM core: 128x128 block tile, BK=8, 256 threads, 8x8 per thread.
// TRANS_B: B is [N,K] row-major (dot of rows) instead of [K,N].
// EPI_MASK: C = acc*scale + mask[m, n]  (mask row-major with ld=ldm)
// Assumes M%128==0, N%128==0, K%8==0, all pointers 16B aligned, lds %4==0.
// ---------------------------------------------------------------------------
constexpr int BM = 128, BN = 128, BK = 8, TM = 8, TN = 8;

template <bool TRANS_B, bool EPI_MASK>
__device__ __forceinline__ void gemm_tile(
    const float* __restrict__ A, const float* __restrict__ B, float* __restrict__ C,
    int K, int lda, int ldb, int ldc,
    float scale, const float* __restrict__ mask, int ldm)
{
    __shared__ float As[BK][BM + 4];
    __shared__ float Bs[BK][BN + 4];

    const int tid = threadIdx.x;          // 0..255
    const int tx  = tid & 15;             // 0..15
    const int ty  = tid >> 4;             // 0..15

    const long long brow = (long long)blockIdx.y * BM;
    const long long bcol = (long long)blockIdx.x * BN;

    // A-load mapping: 128 rows x 8 cols, float4 per thread
    const int arow = tid >> 1;            // 0..127
    const int acol = (tid & 1) * 4;       // 0 or 4
    // B-load mapping (NN): 8 rows x 128 cols
    const int bkr = tid >> 5;             // 0..7
    const int bnc = (tid & 31) * 4;       // 0..124

    float acc[TM][TN];
#pragma unroll
    for (int i = 0; i < TM; i++)
#pragma unroll
        for (int j = 0; j < TN; j++) acc[i][j] = 0.0f;

    for (int k0 = 0; k0 < K; k0 += BK) {
        // Stage A (transposed into As[k][m])
        float4 av = *reinterpret_cast<const float4*>(
            A + (brow + arow) * (long long)lda + k0 + acol);
        As[acol + 0][arow] = av.x;
        As[acol + 1][arow] = av.y;
        As[acol + 2][arow] = av.z;
        As[acol + 3][arow] = av.w;

        if (TRANS_B) {
            float4 bv = *reinterpret_cast<const float4*>(
                B + (bcol + arow) * (long long)ldb + k0 + acol);
            Bs[acol + 0][arow] = bv.x;
            Bs[acol + 1][arow] = bv.y;
            Bs[acol + 2][arow] = bv.z;
            Bs[acol + 3][arow] = bv.w;
        } else {
            float4 bv = *reinterpret_cast<const float4*>(
                B + (long long)(k0 + bkr) * ldb + bcol + bnc);
            Bs[bkr][bnc + 0] = bv.x;
            Bs[bkr][bnc + 1] = bv.y;
            Bs[bkr][bnc + 2] = bv.z;
            Bs[bkr][bnc + 3] = bv.w;
        }
        __syncthreads();

#pragma unroll
        for (int kk = 0; kk < BK; kk++) {
            float a[TM], b[TN];
#pragma unroll
            for (int i = 0; i < TM; i++) a[i] = As[kk][ty * TM + i];
#pragma unroll
            for (int j = 0; j < TN; j++) b[j] = Bs[kk][tx * TN + j];
#pragma unroll
            for (int i = 0; i < TM; i++)
#pragma unroll
                for (int j = 0; j < TN; j++)
                    acc[i][j] = fmaf(a[i], b[j], acc[i][j]);
        }
        __syncthreads();
    }

    // Epilogue
#pragma unroll
    for (int i = 0; i < TM; i++) {
        long long row = brow + ty * TM + i;
        long long col = bcol + tx * TN;
        float4 v0, v1;
        if (EPI_MASK) {
            const float* mrow = mask + row * (long long)ldm + col;
            v0.x = acc[i][0] * scale + mrow[0];
            v0.y = acc[i][1] * scale + mrow[1];
            v0.z = acc[i][2] * scale + mrow[2];
            v0.w = acc[i][3] * scale + mrow[3];
            v1.x = acc[i][4] * scale + mrow[4];
            v1.y = acc[i][5] * scale + mrow[5];
            v1.z = acc[i][6] * scale + mrow[6];
            v1.w = acc[i][7] * scale + mrow[7];
        } else {
            v0.x = acc[i][0]; v0.y = acc[i][1]; v0.z = acc[i][2]; v0.w = acc[i][3];
            v1.x = acc[i][4]; v1.y = acc[i][5]; v1.z = acc[i][6]; v1.w = acc[i][7];
        }
        float* crow = C + row * (long long)ldc + col;
        *reinterpret_cast<float4*>(crow)     = v0;
        *reinterpret_cast<float4*>(crow + 4) = v1;
    }
}

// Generic NN GEMM with per-z pointer strides (projections)
__global__ void __launch_bounds__(256)
sgemm_nn_kernel(const float* __restrict__ A, const float* __restrict__ B,
                float* __restrict__ C, int K, int lda, int ldb, int ldc,
                long long sA, long long sB, long long sC)
{
    gemm_tile<false, false>(A + blockIdx.z * sA, B + blockIdx.z * sB,
                            C + blockIdx.z * sC, K, lda, ldb, ldc,
                            1.0f, nullptr, 0);
}

// scores[b,h,q,k] = scale * Q[b,q,h,:]·K[b,k,:] + mask[b,q,k]
__global__ void __launch_bounds__(256)
attn_scores_kernel(const float* __restrict__ Q, const float* __restrict__ Kb,
                   const float* __restrict__ mask, float* __restrict__ S)
{
    int z = blockIdx.z;          // b*H + h
    int b = z >> 3;
    int h = z & 7;
    gemm_tile<true, true>(
        Q + (long long)b * Lt * HH + (long long)h * HD,
        Kb + (long long)b * Lt * HD,
        S + (long long)z * Lt * Lt,
        HD, HH, HD, Lt,
        0.0625f /* 1/sqrt(256) */,
        mask + (long long)b * Lt * Lt, Lt);
}

// AO[b,q,h,:] = P[b,h,q,:] @ V[b,:,:]
__global__ void __launch_bounds__(256)
attn_pv_kernel(const float* __restrict__ S, const float* __restrict__ V,
               float* __restrict__ AO)
{
    int z = blockIdx.z;
    int b = z >> 3;
    int h = z & 7;
    gemm_tile<false, false>(
        S + (long long)z * Lt * Lt,
        V + (long long)b * Lt * HD,
        AO + (long long)b * Lt * HH + (long long)h * HD,
        Lt, Lt, HD, HH,
        1.0f, nullptr, 0);
}

// ---------------------------------------------------------------------------
// RoPE (Gemma half-split) applied in place to Q (all heads) and K (1 kv head).
// One block per (b,l), 128 threads (= HD/2).
// ---------------------------------------------------------------------------
__global__ void __launch_bounds__(128)
rope_kernel(float* __restrict__ Q, float* __restrict__ Kb,
            const int* __restrict__ pos)
{
    const int bl = blockIdx.x;               // b*Lt + l
    const int i  = threadIdx.x;              // 0..127
    const float p = (float)pos[bl];
    // inv_freq = 10000^(-i/128)
    const float inv = powf(10000.0f, -(float)i * (1.0f / 128.0f));
    const float f = p * inv;
    float s, c;
    sincosf(f, &s, &c);

    // Q: 8 heads
    float* qb = Q + (long long)bl * HH;
#pragma unroll
    for (int h = 0; h < Hh; h++) {
        float x1 = qb[h * HD + i];
        float x2 = qb[h * HD + 128 + i];
        qb[h * HD + i]       = x1 * c - x2 * s;
        qb[h * HD + 128 + i] = x2 * c + x1 * s;
    }
    // K: 1 kv head
    float* kb = Kb + (long long)bl * HD;
    float x1 = kb[i];
    float x2 = kb[128 + i];
    kb[i]       = x1 * c - x2 * s;
    kb[128 + i] = x2 * c + x1 * s;
}

// ---------------------------------------------------------------------------
// Row softmax over S: B*H*Lt rows of length Lt. Block(256) per row.
// ---------------------------------------------------------------------------
__global__ void __launch_bounds__(256)
softmax_kernel(float* __restrict__ S)
{
    __shared__ float red[256];
    float* p = S + (long long)blockIdx.x * Lt;
    const int t = threadIdx.x;

    float x0 = p[t], x1 = p[t + 256], x2 = p[t + 512], x3 = p[t + 768];

    float m = fmaxf(fmaxf(x0, x1), fmaxf(x2, x3));
    red[t] = m;
    __syncthreads();
    for (int s = 128; s > 0; s >>= 1) {
        if (t < s) red[t] = fmaxf(red[t], red[t + s]);
        __syncthreads();
    }
    m = red[0];
    __syncthreads();

    x0 = expf(x0 - m); x1 = expf(x1 - m); x2 = expf(x2 - m); x3 = expf(x3 - m);
    red[t] = x0 + x1 + x2 + x3;
    __syncthreads();
    for (int s = 128; s > 0; s >>= 1) {
        if (t < s) red[t] += red[t + s];
        __syncthreads();
    }
    const float inv = 1.0f / red[0];

    p[t]       = x0 * inv;
    p[t + 256] = x1 * inv;
    p[t + 512] = x2 * inv;
    p[t + 768] = x3 * inv;
}

// ---------------------------------------------------------------------------
// Host launcher
// ---------------------------------------------------------------------------
static inline void launch_nn(const float* A, const float* B, float* C,
                             int M, int N, int K, int lda, int ldb, int ldc,
                             long long sA, long long sB, long long sC, int Z)
{
    dim3 grid(N / BN, M / BM, Z);
    sgemm_nn_kernel<<<grid, 256>>>(A, B, C, K, lda, ldb, ldc, sA, sB, sC);
}

extern "C" void kernel_launch(void* const* d_in, const int* in_sizes, int n_in,
                              void* d_out, int out_size)
{
    const float* pali   = (const float*)d_in[0];
    const float* expert = (const float*)d_in[1];
    const int*   pos    = (const int*)d_in[2];
    const float* mask   = (const float*)d_in[3];
    // d_in[4] = use_cache (always 0 here, prefill path) — ignored
    const float* wq_p = (const float*)d_in[5];
    const float* wk_p = (const float*)d_in[6];
    const float* wv_p = (const float*)d_in[7];
    const float* wo_p = (const float*)d_in[8];
    const float* wq_e = (const float*)d_in[9];
    const float* wk_e = (const float*)d_in[10];
    const float* wv_e = (const float*)d_in[11];
    const float* wo_e = (const float*)d_in[12];

    float* out   = (float*)d_out;
    float* out_p = out;
    float* out_e = out + (long long)Bb * LP * DP;

    float *Q, *K, *V, *S, *AO;
    cudaGetSymbolAddress((void**)&Q,  g_Q);
    cudaGetSymbolAddress((void**)&K,  g_K);
    cudaGetSymbolAddress((void**)&V,  g_V);
    cudaGetSymbolAddress((void**)&S,  g_S);
    cudaGetSymbolAddress((void**)&AO, g_AO);

    // --- QKV projections (pali stream: rows [0,768), expert: rows [768,1024)) ---
    // pali
    launch_nn(pali, wq_p, Q, LP, HH, DP, DP, HH, HH,
              (long long)LP * DP, 0, (long long)Lt * HH, Bb);
    launch_nn(pali, wk_p, K, LP, HD, DP, DP, HD, HD,
              (long long)LP * DP, 0, (long long)Lt * HD, Bb);
    launch_nn(pali, wv_p, V, LP, HD, DP, DP, HD, HD,
              (long long)LP * DP, 0, (long long)Lt * HD, Bb);
    // expert
    launch_nn(expert, wq_e, Q + (long long)LP * HH, LE, HH, DE, DE, HH, HH,
              (long long)LE * DE, 0, (long long)Lt * HH, Bb);
    launch_nn(expert, wk_e, K + (long long)LP * HD, LE, HD, DE, DE, HD, HD,
              (long long)LE * DE, 0, (long long)Lt * HD, Bb);
    launch_nn(expert, wv_e, V + (long long)LP * HD, LE, HD, DE, DE, HD, HD,
              (long long)LE * DE, 0, (long long)Lt * HD, Bb);

    // --- RoPE on Q and K ---
    rope_kernel<<<Bb * Lt, 128>>>(Q, K, pos);

    // --- scores = scale * Q K^T + mask ---
    {
        dim3 grid(Lt / BN, Lt / BM, Bb * Hh);
        attn_scores_kernel<<<grid, 256>>>(Q, K, mask, S);
    }

    // --- softmax over k ---
    softmax_kernel<<<Bb * Hh * Lt, 256>>>(S);

    // --- AO = P @ V ---
    {
        dim3 grid(HD / BN, Lt / BM, Bb * Hh);
        attn_pv_kernel<<<grid, 256>>>(S, V, AO);
    }

    // --- output projections ---
    launch_nn(AO, wo_p, out_p, LP, DP, HH, HH, DP, DP,
              (long long)Lt * HH, 0, (long long)LP * DP, Bb);
    launch_nn(AO + (long long)LP * HH, wo_e, out_e, LE, DE, HH, HH, DE, DE,
              (long long)Lt * HH, 0, (long long)LE * DE, Bb);
}

// round 2
// speedup vs baseline: 1.0003x; 1.0003x over previous
#include <cuda_runtime.h>
#include <cuda_bf16.h>
#include <math.h>

// Problem constants
constexpr int Bb  = 4;
constexpr int LP  = 768;
constexpr int LE  = 256;
constexpr int Lt  = 1024;   // LP + LE
constexpr int DP  = 2048;
constexpr int DE  = 1024;
constexpr int Hh  = 8;
constexpr int HD  = 256;
constexpr int HH  = 2048;   // H * HD

// Scratch (allocation-free: static device globals)
__device__ float g_Q[(size_t)Bb * Lt * HH];        // 8.4M floats
__device__ float g_K[(size_t)Bb * Lt * HD];        // 1M
__device__ float g_V[(size_t)Bb * Lt * HD];        // 1M
__device__ float g_S[(size_t)Bb * Hh * Lt * Lt];   // 33.5M (scores / probs)
__device__ float g_AO[(size_t)Bb * Lt * HH];       // 8.4M (attention output)

// ---------------------------------------------------------------------------
// Tiled SGEMM core: 128x128 block tile, BK=8, 256 threads, 8x8 per thread.
// TRANS_B: B is [N,K] row-major (dot of rows) instead of [K,N].
// EPI_MASK: C = acc*scale + mask[m, n]  (mask row-major with ld=ldm)
// Assumes M%128==0, N%128==0, K%8==0, all pointers 16B aligned, lds %4==0.
// ---------------------------------------------------------------------------
constexpr int BM = 128, BN = 128, BK = 8, TM = 8, TN = 8;

template <bool TRANS_B, bool EPI_MASK>
__device__ __forceinline__ void gemm_tile(
    const float* __restrict__ A, const float* __restrict__ B, float* __restrict__ C,
    int K, int lda, int ldb, int ldc,
    float scale, const float* __restrict__ mask, int ldm)
{
    __shared__ float As[BK][BM + 4];
    __shared__ float Bs[BK][BN + 4];

    const int tid = threadIdx.x;          // 0..255
    const int tx  = tid & 15;             // 0..15
    const int ty  = tid >> 4;             // 0..15

    const long long brow = (long long)blockIdx.y * BM;
    const long long bcol = (long long)blockIdx.x * BN;

    // A-load mapping: 128 rows x 8 cols, float4 per thread
    const int arow = tid >> 1;            // 0..127
    const int acol = (tid & 1) * 4;       // 0 or 4
    // B-load mapping (NN): 8 rows x 128 cols
    const int bkr = tid >> 5;             // 0..7
    const int bnc = (tid & 31) * 4;       // 0..124

    float acc[TM][TN];
#pragma unroll
    for (int i = 0; i < TM; i++)
#pragma unroll
        for (int j = 0; j < TN; j++) acc[i][j] = 0.0f;

    for (int k0 = 0; k0 < K; k0 += BK) {
        // Stage A (transposed into As[k][m])
        float4 av = *reinterpret_cast<const float4*>(
            A + (brow + arow) * (long long)lda + k0 + acol);
        As[acol + 0][arow] = av.x;
        As[acol + 1][arow] = av.y;
        As[acol + 2][arow] = av.z;
        As[acol + 3][arow] = av.w;

        if (TRANS_B) {
            float4 bv = *reinterpret_cast<const float4*>(
                B + (bcol + arow) * (long long)ldb + k0 + acol);
            Bs[acol + 0][arow] = bv.x;
            Bs[acol + 1][arow] = bv.y;
            Bs[acol + 2][arow] = bv.z;
            Bs[acol + 3][arow] = bv.w;
        } else {
            float4 bv = *reinterpret_cast<const float4*>(
                B + (long long)(k0 + bkr) * ldb + bcol + bnc);
            Bs[bkr][bnc + 0] = bv.x;
            Bs[bkr][bnc + 1] = bv.y;
            Bs[bkr][bnc + 2] = bv.z;
            Bs[bkr][bnc + 3] = bv.w;
        }
        __syncthreads();

#pragma unroll
        for (int kk = 0; kk < BK; kk++) {
            float a[TM], b[TN];
#pragma unroll
            for (int i = 0; i < TM; i++) a[i] = As[kk][ty * TM + i];
#pragma unroll
            for (int j = 0; j < TN; j++) b[j] = Bs[kk][tx * TN + j];
#pragma unroll
            for (int i = 0; i < TM; i++)
#pragma unroll
                for (int j = 0; j < TN; j++)
                    acc[i][j] = fmaf(a[i], b[j], acc[i][j]);
        }
        __syncthreads();
    }

    // Epilogue
#pragma unroll
    for (int i = 0; i < TM; i++) {
        long long row = brow + ty * TM + i;
        long long col = bcol + tx * TN;
        float4 v0, v1;
        if (EPI_MASK) {
            const float* mrow = mask + row * (long long)ldm + col;
            v0.x = acc[i][0] * scale + mrow[0];
            v0.y = acc[i][1] * scale + mrow[1];
            v0.z = acc[i][2] * scale + mrow[2];
            v0.w = acc[i][3] * scale + mrow[3];
            v1.x = acc[i][4] * scale + mrow[4];
            v1.y = acc[i][5] * scale + mrow[5];
            v1.z = acc[i][6] * scale + mrow[6];
            v1.w = acc[i][7] * scale + mrow[7];
        } else {
            v0.x = acc[i][0]; v0.y = acc[i][1]; v0.z = acc[i][2]; v0.w = acc[i][3];
            v1.x = acc[i][4]; v1.y = acc[i][5]; v1.z = acc[i][6]; v1.w = acc[i][7];
        }
        float* crow = C + row * (long long)ldc + col;
        *reinterpret_cast<float4*>(crow)     = v0;
        *reinterpret_cast<float4*>(crow + 4) = v1;
    }
}

// Generic NN GEMM with per-z pointer strides (projections)
__global__ void __launch_bounds__(256)
sgemm_nn_kernel(const float* __restrict__ A, const float* __restrict__ B,
                float* __restrict__ C, int K, int lda, int ldb, int ldc,
                long long sA, long long sB, long long sC)
{
    gemm_tile<false, false>(A + blockIdx.z * sA, B + blockIdx.z * sB,
                            C + blockIdx.z * sC, K, lda, ldb, ldc,
                            1.0f, nullptr, 0);
}

// scores[b,h,q,k] = scale * Q[b,q,h,:]·K[b,k,:] + mask[b,q,k]
__global__ void __launch_bounds__(256)
attn_scores_kernel(const float* __restrict__ Q, const float* __restrict__ Kb,
                   const float* __restrict__ mask, float* __restrict__ S)
{
    int z = blockIdx.z;          // b*H + h
    int b = z >> 3;
    int h = z & 7;
    gemm_tile<true, true>(
        Q + (long long)b * Lt * HH + (long long)h * HD,
        Kb + (long long)b * Lt * HD,
        S + (long long)z * Lt * Lt,
        HD, HH, HD, Lt,
        0.0625f /* 1/sqrt(256) */,
        mask + (long long)b * Lt * Lt, Lt);
}

// AO[b,q,h,:] = P[b,h,q,:] @ V[b,:,:]
__global__ void __launch_bounds__(256)
attn_pv_kernel(const float* __restrict__ S, const float* __restrict__ V,
               float* __restrict__ AO)
{
    int z = blockIdx.z;
    int b = z >> 3;
    int h = z & 7;
    gemm_tile<false, false>(
        S + (long long)z * Lt * Lt,
        V + (long long)b * Lt * HD,
        AO + (long long)b * Lt * HH + (long long)h * HD,
        Lt, Lt, HD, HH,
        1.0f, nullptr, 0);
}

// ---------------------------------------------------------------------------
// RoPE (Gemma half-split) applied in place to Q (all heads) and K (1 kv head).
// One block per (b,l), 128 threads (= HD/2).
// ---------------------------------------------------------------------------
__global__ void __launch_bounds__(128)
rope_kernel(float* __restrict__ Q, float* __restrict__ Kb,
            const int* __restrict__ pos)
{
    const int bl = blockIdx.x;               // b*Lt + l
    const int i  = threadIdx.x;              // 0..127
    const float p = (float)pos[bl];
    // inv_freq = 10000^(-i/128)
    const float inv = powf(10000.0f, -(float)i * (1.0f / 128.0f));
    const float f = p * inv;
    float s, c;
    sincosf(f, &s, &c);

    // Q: 8 heads
    float* qb = Q + (long long)bl * HH;
#pragma unroll
    for (int h = 0; h < Hh; h++) {
        float x1 = qb[h * HD + i];
        float x2 = qb[h * HD + 128 + i];
        qb[h * HD + i]       = x1 * c - x2 * s;
        qb[h * HD + 128 + i] = x2 * c + x1 * s;
    }
    // K: 1 kv head
    float* kb = Kb + (long long)bl * HD;
    float x1 = kb[i];
    float x2 = kb[128 + i];
    kb[i]       = x1 * c - x2 * s;
    kb[128 + i] = x2 * c + x1 * s;
}

// ---------------------------------------------------------------------------
// Row softmax over S: B*H*Lt rows of length Lt. Block(256) per row.
// ---------------------------------------------------------------------------
__global__ void __launch_bounds__(256)
softmax_kernel(float* __restrict__ S)
{
    __shared__ float red[256];
    float* p = S + (long long)blockIdx.x * Lt;
    const int t = threadIdx.x;

    float x0 = p[t], x1 = p[t + 256], x2 = p[t + 512], x3 = p[t + 768];

    float m = fmaxf(fmaxf(x0, x1), fmaxf(x2, x3));
    red[t] = m;
    __syncthreads();
    for (int s = 128; s > 0; s >>= 1) {
        if (t < s) red[t] = fmaxf(red[t], red[t + s]);
        __syncthreads();
    }
    m = red[0];
    __syncthreads();

    x0 = expf(x0 - m); x1 = expf(x1 - m); x2 = expf(x2 - m); x3 = expf(x3 - m);
    red[t] = x0 + x1 + x2 + x3;
    __syncthreads();
    for (int s = 128; s > 0; s >>= 1) {
        if (t < s) red[t] += red[t + s];
        __syncthreads();
    }
    const float inv = 1.0f / red[0];

    p[t]       = x0 * inv;
    p[t + 256] = x1 * inv;
    p[t + 512] = x2 * inv;
    p[t + 768] = x3 * inv;
}

// ---------------------------------------------------------------------------
// Host launcher
// ---------------------------------------------------------------------------
static inline void launch_nn(const float* A, const float* B, float* C,
                             int M, int N, int K, int lda, int ldb, int ldc,
                             long long sA, long long sB, long long sC, int Z)
{
    dim3 grid(N / BN, M / BM, Z);
    sgemm_nn_kernel<<<grid, 256>>>(A, B, C, K, lda, ldb, ldc, sA, sB, sC);
}

extern "C" void kernel_launch(void* const* d_in, const int* in_sizes, int n_in,
                              void* d_out, int out_size)
{
    const float* pali   = (const float*)d_in[0];
    const float* expert = (const float*)d_in[1];
    const int*   pos    = (const int*)d_in[2];
    const float* mask   = (const float*)d_in[3];
    // d_in[4] = use_cache (always 0 here, prefill path) — ignored
    const float* wq_p = (const float*)d_in[5];
    const float* wk_p = (const float*)d_in[6];
    const float* wv_p = (const float*)d_in[7];
    const float* wo_p = (const float*)d_in[8];
    const float* wq_e = (const float*)d_in[9];
    const float* wk_e = (const float*)d_in[10];
    const float* wv_e = (const float*)d_in[11];
    const float* wo_e = (const float*)d_in[12];

    float* out   = (float*)d_out;
    float* out_p = out;
    float* out_e = out + (long long)Bb * LP * DP;

    float *Q, *K, *V, *S, *AO;
    cudaGetSymbolAddress((void**)&Q,  g_Q);
    cudaGetSymbolAddress((void**)&K,  g_K);
    cudaGetSymbolAddress((void**)&V,  g_V);
    cudaGetSymbolAddress((void**)&S,  g_S);
    cudaGetSymbolAddress((void**)&AO, g_AO);

    // --- QKV projections (pali stream: rows [0,768), expert: rows [768,1024)) ---
    // pali
    launch_nn(pali, wq_p, Q, LP, HH, DP, DP, HH, HH,
              (long long)LP * DP, 0, (long long)Lt * HH, Bb);
    launch_nn(pali, wk_p, K, LP, HD, DP, DP, HD, HD,
              (long long)LP * DP, 0, (long long)Lt * HD, Bb);
    launch_nn(pali, wv_p, V, LP, HD, DP, DP, HD, HD,
              (long long)LP * DP, 0, (long long)Lt * HD, Bb);
    // expert
    launch_nn(expert, wq_e, Q + (long long)LP * HH, LE, HH, DE, DE, HH, HH,
              (long long)LE * DE, 0, (long long)Lt * HH, Bb);
    launch_nn(expert, wk_e, K + (long long)LP * HD, LE, HD, DE, DE, HD, HD,
              (long long)LE * DE, 0, (long long)Lt * HD, Bb);
    launch_nn(expert, wv_e, V + (long long)LP * HD, LE, HD, DE, DE, HD, HD,
              (long long)LE * DE, 0, (long long)Lt * HD, Bb);

    // --- RoPE on Q and K ---
    rope_kernel<<<Bb * Lt, 128>>>(Q, K, pos);

    // --- scores = scale * Q K^T + mask ---
    {
        dim3 grid(Lt / BN, Lt / BM, Bb * Hh);
        attn_scores_kernel<<<grid, 256>>>(Q, K, mask, S);
    }

    // --- softmax over k ---
    softmax_kernel<<<Bb * Hh * Lt, 256>>>(S);

    // --- AO = P @ V ---
    {
        dim3 grid(HD / BN, Lt / BM, Bb * Hh);
        attn_pv_kernel<<<grid, 256>>>(S, V, AO);
    }

    // --- output projections ---
    launch_nn(AO, wo_p, out_p, LP, DP, HH, HH, DP, DP,
              (long long)Lt * HH, 0, (long long)LP * DP, Bb);
    launch_nn(AO + (long long)LP * HH, wo_e, out_e, LE, DE, HH, HH, DE, DE,
              (long long)Lt * HH, 0, (long long)LE * DE, Bb);
}